// round 13
// baseline (speedup 1.0000x reference)
#include <cuda_runtime.h>
#include <cstdint>

#define B_   64
#define T_   1024
#define F_   256
#define U_   512
#define G_   1536             // 3*U
#define P_   1024             // 2*U
#define GB_  (G_*B_)          // 98304
#define HB_  (U_*B_)          // 32768 floats per h ping-pong buffer
#define EPS_ 1e-3f

// ---------------------------------------------------------------------------
// Scratch: __device__ globals (allocation-free per harness rules)
// ---------------------------------------------------------------------------
__device__ float g_xwf[(size_t)T_ * G_ * B_];   // [T][G][B]  x@Wf + bi_f
__device__ float g_xwb[(size_t)T_ * G_ * B_];   // [T][G][B]  x@Wb + bi_b
__device__ float g_resid[(size_t)B_ * T_ * P_]; // [B*T][P]   x@Wp
__device__ float g_hf[(size_t)B_ * T_ * U_];    // [B][T][U]
__device__ float g_hb[(size_t)B_ * T_ * U_];    // [B][T][U]
// h ping-pong: [dir][parity], float2 H[kp=256][b=64], element {h[2kp][b], h[2kp+1][b]}
__device__ float g_hbuf[2 * 2 * HB_];
__device__ unsigned g_flag[2][64];              // per-block monotonic step flags

// ---------------------------------------------------------------------------
// f32x2 packed FMA (Blackwell dual-fp32; only reachable via PTX)
// ---------------------------------------------------------------------------
__device__ __forceinline__ void fma2(float2& d, float2 a, float2 b) {
    unsigned long long& dd = reinterpret_cast<unsigned long long&>(d);
    unsigned long long& aa = reinterpret_cast<unsigned long long&>(a);
    unsigned long long& bb = reinterpret_cast<unsigned long long&>(b);
    asm("fma.rn.f32x2 %0, %1, %2, %0;" : "+l"(dd) : "l"(aa), "l"(bb));
}
__device__ __forceinline__ float2 dup2(float x) { return make_float2(x, x); }

__device__ __forceinline__ unsigned ld_acq(const unsigned* p) {
    unsigned v;
    asm volatile("ld.acquire.gpu.global.u32 %0, [%1];" : "=r"(v) : "l"(p) : "memory");
    return v;
}
__device__ __forceinline__ void st_rel(unsigned* p, unsigned v) {
    asm volatile("st.release.gpu.global.u32 [%0], %1;" :: "l"(p), "r"(v) : "memory");
}

// ---------------------------------------------------------------------------
__global__ void init_kernel() {
    int idx = blockIdx.x * blockDim.x + threadIdx.x;
    int stride = gridDim.x * blockDim.x;
    for (int i = idx; i < 2 * 2 * HB_; i += stride) g_hbuf[i] = 0.0f;
    if (idx < 128) ((unsigned*)g_flag)[idx] = 0u;
}

// ---------------------------------------------------------------------------
// GEMM core: 64x64 tile, BK=16, 256 threads.
// ---------------------------------------------------------------------------
__device__ __forceinline__ void gemm_tile(
    const float* __restrict__ A, const float* __restrict__ Bw, int N,
    int row0, int col0, float2 acc[4][2],
    float (*As)[64], float (*Bs)[64])
{
    int tid  = threadIdx.x;
    int tx   = tid & 15;
    int ty   = tid >> 4;
    int lrow = tid >> 2;
    int lkq  = (tid & 3) * 4;
    int lk   = tid >> 4;
    int lnq  = (tid & 15) * 4;

#pragma unroll
    for (int i = 0; i < 4; i++) { acc[i][0] = make_float2(0.f, 0.f); acc[i][1] = make_float2(0.f, 0.f); }

    for (int k0 = 0; k0 < F_; k0 += 16) {
        float4 av = *(const float4*)(A + (size_t)(row0 + lrow) * F_ + k0 + lkq);
        As[lkq + 0][lrow] = av.x;
        As[lkq + 1][lrow] = av.y;
        As[lkq + 2][lrow] = av.z;
        As[lkq + 3][lrow] = av.w;
        *(float4*)(&Bs[lk][lnq]) = *(const float4*)(Bw + (size_t)(k0 + lk) * N + col0 + lnq);
        __syncthreads();

#pragma unroll
        for (int kk = 0; kk < 16; kk++) {
            float4 a4 = *(const float4*)(&As[kk][ty * 4]);
            float4 b4 = *(const float4*)(&Bs[kk][tx * 4]);
            float2 bp0 = make_float2(b4.x, b4.y);
            float2 bp1 = make_float2(b4.z, b4.w);
            float aa[4] = {a4.x, a4.y, a4.z, a4.w};
#pragma unroll
            for (int i = 0; i < 4; i++) {
                float2 ad = dup2(aa[i]);
                fma2(acc[i][0], ad, bp0);
                fma2(acc[i][1], ad, bp1);
            }
        }
        __syncthreads();
    }
}

// Fused xw GEMMs (Wf and Wb): blockIdx.y in [0,48). y<24 -> Wf, else Wb.
__global__ void __launch_bounds__(256) gemm_xw_kernel(
    const float* __restrict__ x,
    const float* __restrict__ Wf, const float* __restrict__ Wb,
    const float* __restrict__ bf, const float* __restrict__ bb)
{
    __shared__ float As[16][64];
    __shared__ float Bs[16][64];
    int ysel = blockIdx.y >= 24;
    const float* Bw   = ysel ? Wb : Wf;
    const float* bias = ysel ? bb : bf;
    float* outp       = ysel ? g_xwb : g_xwf;
    int row0 = blockIdx.x * 64;
    int col0 = (blockIdx.y - (ysel ? 24 : 0)) * 64;

    float2 acc[4][2];
    gemm_tile(x, Bw, G_, row0, col0, acc, As, Bs);

    int tx = threadIdx.x & 15, ty = threadIdx.x >> 4;
#pragma unroll
    for (int i = 0; i < 4; i++) {
        int r = row0 + ty * 4 + i;
        int b = r >> 10;
        int t = r & 1023;
        int c = col0 + tx * 4;
        float v[4] = {acc[i][0].x, acc[i][0].y, acc[i][1].x, acc[i][1].y};
#pragma unroll
        for (int j = 0; j < 4; j++) {
            int g = c + j;
            outp[(size_t)t * GB_ + (size_t)g * B_ + b] = v[j] + bias[g];
        }
    }
}

// Residual projection GEMM (Wp)
__global__ void __launch_bounds__(256) gemm_p_kernel(
    const float* __restrict__ x, const float* __restrict__ Wp)
{
    __shared__ float As[16][64];
    __shared__ float Bs[16][64];
    int row0 = blockIdx.x * 64;
    int col0 = blockIdx.y * 64;

    float2 acc[4][2];
    gemm_tile(x, Wp, P_, row0, col0, acc, As, Bs);

    int tx = threadIdx.x & 15, ty = threadIdx.x >> 4;
#pragma unroll
    for (int i = 0; i < 4; i++) {
        int r = row0 + ty * 4 + i;
        int c = col0 + tx * 4;
        g_resid[(size_t)r * P_ + c + 0] = acc[i][0].x;
        g_resid[(size_t)r * P_ + c + 1] = acc[i][0].y;
        g_resid[(size_t)r * P_ + c + 2] = acc[i][1].x;
        g_resid[(size_t)r * P_ + c + 3] = acc[i][1].y;
    }
}

// ---------------------------------------------------------------------------
// GRU recurrence v13: flag-array sync (no atomics, no IVALL) + L2-direct h.
// 128 blocks: 0..63 fwd, 64..127 bwd. Block owns 8 units of its direction.
// 512 threads = 16 warps: warp w -> (ch=w&1: col half = 12 U-cols,
// kw=w>>1: k-eighth = 32 kp). Lane covers batches (2*lane, 2*lane+1).
// Sync: producer writes monotonic g_flag[dir][jb]=s+1 (st.release, no
// contention); consumers: threads 0..63 poll one flag each (ld.acquire) in
// parallel, then __syncthreads. h reads use __ldcg (L2-direct) so NO L1
// invalidate / threadfence is needed on the consumer path.
// h tile in 8 bursts of 4 LDG.128, triple-buffered (prefetch distance 2).
// SMEM: U 48KB [24][512] + partials 48KB [16][12][64] = 96KB.
// ---------------------------------------------------------------------------
__global__ void __launch_bounds__(512) gru_kernel(
    const float* __restrict__ Ufm, const float* __restrict__ Ubm,
    const float* __restrict__ bfv, const float* __restrict__ bbv)
{
    extern __shared__ float smem_[];
    float* Us   = smem_;                         // [24][512]
    float* part = smem_ + 24 * 512;              // [16][12][64]
#define PARTF(w, c, b) part[(((w) * 12 + (c)) << 6) + (b)]

    int tid = threadIdx.x;
    int dir = blockIdx.x >> 6;
    int jb  = blockIdx.x & 63;

    const float* Um    = dir ? Ubm : Ufm;
    const float* brv   = (dir ? bbv : bfv) + G_;   // recurrent bias b[1]
    const float* xw    = dir ? g_xwb : g_xwf;
    float*       hout  = dir ? g_hb  : g_hf;
    float*       hbase = g_hbuf + (size_t)dir * 2 * HB_;

    // Load U slice: col c = gate*8+uu -> Um[:, gate*512 + jb*8 + uu]
    for (int idx = tid; idx < 24 * 512; idx += 512) {
        int c = idx >> 9;
        int k = idx & 511;
        int g  = c >> 3;
        int uu = c & 7;
        Us[c * 512 + k] = Um[(size_t)k * G_ + g * U_ + jb * 8 + uu];
    }

    // compute role
    int w    = tid >> 5;        // 0..15
    int lane = tid & 31;
    int ch   = w & 1;           // col half: cols [ch*12, ch*12+12)
    int kw   = w >> 1;          // k-eighth: kp in [kw*32, kw*32+32)
    int cbase = ch * 12;

    // finalize role
    int uf   = tid >> 6;        // 0..7
    int bfin = tid & 63;
    int fug  = jb * 8 + uf;
    float brz = brv[fug];
    float brr = brv[U_ + fug];
    float brh = brv[2 * U_ + fug];
    // finalize col mapping: z col = uf (half 0), r col = 8+uf, h col = 16+uf (half 1)
    int chr = (uf >= 4) ? 1 : 0;
    int clr = (uf >= 4) ? (uf - 4) : (8 + uf);

    const float4* U4 = (const float4*)Us;   // index: c*128 + kw*16 + jj

    __syncthreads();

    for (int s = 0; s < T_; s++) {
        int tt = dir ? (T_ - 1 - s) : s;
        int par = s & 1;
        const float* HcF = hbase + (size_t)par * HB_;
        float*       HnF = hbase + (size_t)(par ^ 1) * HB_;
        // float4 view of H: index kp*32 + (b/2)
        const float4* Hq = (const float4*)HcF + (size_t)(kw * 32) * 32 + lane;

        // ---- operands that do NOT need the acquire: issue before the wait
        // xw was written before this kernel launched; hold was written by
        // THIS thread last step (same (uf,bfin) mapping).
        const float* XW = xw + (size_t)tt * GB_;
        float xz = __ldg(&XW[(0 * U_ + fug) * B_ + bfin]);
        float xr = __ldg(&XW[(1 * U_ + fug) * B_ + bfin]);
        float xh = __ldg(&XW[(2 * U_ + fug) * B_ + bfin]);
        float2 hv = __ldcg((const float2*)HcF + (size_t)(fug >> 1) * 64 + bfin);
        float hold = (uf & 1) ? hv.y : hv.x;

        // ---- wait: threads 0..63 each poll ONE producer flag (parallel)
        if (s > 0) {
            if (tid < 64) {
                const unsigned target = (unsigned)s;
                const unsigned* fp = &g_flag[dir][tid];
                while (ld_acq(fp) < target) { }
            }
            __syncthreads();
        }

        // ---- dots: 12 cols x 32 kp x 2 batches per thread ----
        float2 acc0[12], acc1[12];
#pragma unroll
        for (int c = 0; c < 12; c++) { acc0[c] = make_float2(0.f, 0.f); acc1[c] = make_float2(0.f, 0.f); }

        // triple-buffered bursts: 4 float4 per burst = 4 kp; prefetch dist 2
        float4 buf0[4], buf1[4], buf2[4];
#pragma unroll
        for (int j = 0; j < 4; j++) buf0[j] = __ldcg(Hq + (size_t)j * 32);
#pragma unroll
        for (int j = 0; j < 4; j++) buf1[j] = __ldcg(Hq + (size_t)(4 + j) * 32);

#pragma unroll
        for (int seg = 0; seg < 8; seg++) {
            float4* cur = (seg % 3 == 0) ? buf0 : (seg % 3 == 1) ? buf1 : buf2;
            float4* pre = (seg % 3 == 0) ? buf2 : (seg % 3 == 1) ? buf0 : buf1;
            if (seg < 6) {   // prefetch seg+2
#pragma unroll
                for (int j = 0; j < 4; j++)
                    pre[j] = __ldcg(Hq + (size_t)((seg + 2) * 4 + j) * 32);
            }
            // consume: kp 4*seg..4*seg+3 -> U4 indices kw*16 + 2*seg, +1
#pragma unroll
            for (int half = 0; half < 2; half++) {
                float4 h0 = cur[2 * half];       // kp even: b0=.xy b1=.zw
                float4 h1 = cur[2 * half + 1];   // kp odd
#pragma unroll
                for (int c = 0; c < 12; c++) {
                    float4 u = U4[(cbase + c) * 128 + kw * 16 + 2 * seg + half];
                    fma2(acc0[c], make_float2(u.x, u.y), make_float2(h0.x, h0.y));
                    fma2(acc1[c], make_float2(u.x, u.y), make_float2(h0.z, h0.w));
                    fma2(acc0[c], make_float2(u.z, u.w), make_float2(h1.x, h1.y));
                    fma2(acc1[c], make_float2(u.z, u.w), make_float2(h1.z, h1.w));
                }
            }
        }

        // fold even/odd k; write {b0, b1} as one float2
        float2* P2 = (float2*)part;
#pragma unroll
        for (int c = 0; c < 12; c++)
            P2[((w * 12 + c) << 5) + lane] =
                make_float2(acc0[c].x + acc0[c].y, acc1[c].x + acc1[c].y);
        __syncthreads();

        // ---- finalize: thread -> (unit uf, batch bfin) ----
        {
            float sz = 0.f, sr = 0.f, sh = 0.f;
#pragma unroll
            for (int k8 = 0; k8 < 8; k8++) {
                sz += PARTF(2 * k8 + 0,   uf,      bfin);   // z: col uf (half 0)
                sr += PARTF(2 * k8 + chr, clr,     bfin);   // r: col 8+uf
                sh += PARTF(2 * k8 + 1,   4 + uf,  bfin);   // h: col 16+uf (half 1)
            }
            float z  = 1.0f / (1.0f + expf(-(xz + sz + brz)));
            float r  = 1.0f / (1.0f + expf(-(xr + sr + brr)));
            float hh = tanhf(xh + r * (sh + brh));
            float hn = z * hold + (1.0f - z) * hh;

            HnF[(((size_t)(fug >> 1) * 64 + bfin) << 1) + (uf & 1)] = hn;
            __syncthreads();   // all Hn stores issued before release

            // release: fence + monotonic per-block flag (no contention)
            if (tid == 0) {
                __threadfence();
                st_rel(&g_flag[dir][jb], (unsigned)(s + 1));
            }
            // scattered per-timestep output store (overlaps release latency)
            hout[((size_t)bfin * T_ + tt) * U_ + fug] = hn;
        }
    }
#undef PARTF
}

// ---------------------------------------------------------------------------
// Epilogue: y = concat(hf,hb) + resid; LayerNorm over last dim (1024)
// ---------------------------------------------------------------------------
__global__ void __launch_bounds__(256) ln_kernel(
    const float* __restrict__ gamma, const float* __restrict__ beta,
    float* __restrict__ out)
{
    __shared__ float red[2][8];
    int row = blockIdx.x;       // b*T + t
    int tid = threadIdx.x;
    int c   = tid * 4;

    const float* hsrc = (tid < 128)
        ? (g_hf + (size_t)row * U_ + c)
        : (g_hb + (size_t)row * U_ + (c - U_));
    float4 h4 = *(const float4*)hsrc;
    float4 r4 = *(const float4*)(g_resid + (size_t)row * P_ + c);

    float y0 = h4.x + r4.x, y1 = h4.y + r4.y, y2 = h4.z + r4.z, y3 = h4.w + r4.w;
    float s  = y0 + y1 + y2 + y3;
    float s2 = y0 * y0 + y1 * y1 + y2 * y2 + y3 * y3;

#pragma unroll
    for (int off = 16; off > 0; off >>= 1) {
        s  += __shfl_xor_sync(0xFFFFFFFFu, s,  off);
        s2 += __shfl_xor_sync(0xFFFFFFFFu, s2, off);
    }
    int wid = tid >> 5, lane = tid & 31;
    if (lane == 0) { red[0][wid] = s; red[1][wid] = s2; }
    __syncthreads();
    s = 0.f; s2 = 0.f;
#pragma unroll
    for (int i = 0; i < 8; i++) { s += red[0][i]; s2 += red[1][i]; }

    float mu  = s * (1.0f / 1024.0f);
    float var = s2 * (1.0f / 1024.0f) - mu * mu;
    float inv = rsqrtf(var + EPS_);

    float4 g4 = *(const float4*)(gamma + c);
    float4 b4 = *(const float4*)(beta + c);
    float4 o;
    o.x = g4.x * (y0 - mu) * inv + b4.x;
    o.y = g4.y * (y1 - mu) * inv + b4.y;
    o.z = g4.z * (y2 - mu) * inv + b4.z;
    o.w = g4.w * (y3 - mu) * inv + b4.w;
    *(float4*)(out + (size_t)row * P_ + c) = o;
}

// ---------------------------------------------------------------------------
extern "C" void kernel_launch(void* const* d_in, const int* in_sizes, int n_in,
                              void* d_out, int out_size) {
    const float* x     = (const float*)d_in[0];
    const float* Wf    = (const float*)d_in[1];
    const float* Uf    = (const float*)d_in[2];
    const float* bf    = (const float*)d_in[3];
    const float* Wb    = (const float*)d_in[4];
    const float* Ub    = (const float*)d_in[5];
    const float* bb    = (const float*)d_in[6];
    const float* Wp    = (const float*)d_in[7];
    const float* gamma = (const float*)d_in[8];
    const float* beta  = (const float*)d_in[9];
    float* out = (float*)d_out;

    const int gru_smem = 24 * 512 * 4 + 16 * 12 * 64 * 4;  // 49152 + 49152 = 98304 B
    cudaFuncSetAttribute(gru_kernel, cudaFuncAttributeMaxDynamicSharedMemorySize, gru_smem);

    init_kernel<<<64, 256>>>();
    gemm_xw_kernel<<<dim3(1024, 48), 256>>>(x, Wf, Wb, bf, bb);
    gemm_p_kernel<<<dim3(1024, 16), 256>>>(x, Wp);
    gru_kernel<<<128, 512, gru_smem>>>(Uf, Ub, bf, bb);
    ln_kernel<<<B_ * T_, 256>>>(gamma, beta, out);
}

// round 14
// speedup vs baseline: 1.2948x; 1.2948x over previous
#include <cuda_runtime.h>
#include <cstdint>

#define B_   64
#define T_   1024
#define F_   256
#define U_   512
#define G_   1536             // 3*U
#define P_   1024             // 2*U
#define GB_  (G_*B_)          // 98304
#define HB_  (U_*B_)          // 32768 floats per h ping-pong buffer
#define EPS_ 1e-3f

// ---------------------------------------------------------------------------
// Scratch: __device__ globals (allocation-free per harness rules)
// ---------------------------------------------------------------------------
__device__ float g_xwf[(size_t)T_ * G_ * B_];   // [T][G][B]  x@Wf + bi_f
__device__ float g_xwb[(size_t)T_ * G_ * B_];   // [T][G][B]  x@Wb + bi_b
__device__ float g_resid[(size_t)B_ * T_ * P_]; // [B*T][P]   x@Wp
__device__ float g_hf[(size_t)B_ * T_ * U_];    // [B][T][U]
__device__ float g_hb[(size_t)B_ * T_ * U_];    // [B][T][U]
// h ping-pong: [dir][parity], float2 H[kp=256][b=64], element {h[2kp][b], h[2kp+1][b]}
__device__ float g_hbuf[2 * 2 * HB_];
__device__ unsigned g_cnt[2];                   // monotonic arrival counters

// ---------------------------------------------------------------------------
// f32x2 packed FMA (Blackwell dual-fp32; only reachable via PTX)
// ---------------------------------------------------------------------------
__device__ __forceinline__ void fma2(float2& d, float2 a, float2 b) {
    unsigned long long& dd = reinterpret_cast<unsigned long long&>(d);
    unsigned long long& aa = reinterpret_cast<unsigned long long&>(a);
    unsigned long long& bb = reinterpret_cast<unsigned long long&>(b);
    asm("fma.rn.f32x2 %0, %1, %2, %0;" : "+l"(dd) : "l"(aa), "l"(bb));
}
__device__ __forceinline__ float2 dup2(float x) { return make_float2(x, x); }

// ---------------------------------------------------------------------------
__global__ void init_kernel() {
    int idx = blockIdx.x * blockDim.x + threadIdx.x;
    int stride = gridDim.x * blockDim.x;
    for (int i = idx; i < 2 * 2 * HB_; i += stride) g_hbuf[i] = 0.0f;
    if (idx < 2) g_cnt[idx] = 0u;
}

// ---------------------------------------------------------------------------
// GEMM core: 64x64 tile, BK=16, 256 threads, register-staged double buffer.
// ---------------------------------------------------------------------------
__device__ __forceinline__ void gemm_tile(
    const float* __restrict__ A, const float* __restrict__ Bw, int N,
    int row0, int col0, float2 acc[4][2],
    float (*As)[64], float (*Bs)[64])
{
    int tid  = threadIdx.x;
    int tx   = tid & 15;
    int ty   = tid >> 4;
    int lrow = tid >> 2;
    int lkq  = (tid & 3) * 4;
    int lk   = tid >> 4;
    int lnq  = (tid & 15) * 4;

#pragma unroll
    for (int i = 0; i < 4; i++) { acc[i][0] = make_float2(0.f, 0.f); acc[i][1] = make_float2(0.f, 0.f); }

    // preload k0 = 0 into registers
    float4 av = *(const float4*)(A + (size_t)(row0 + lrow) * F_ + lkq);
    float4 bv = *(const float4*)(Bw + (size_t)lk * N + col0 + lnq);

    for (int k0 = 0; k0 < F_; k0 += 16) {
        // stage current tile to smem
        As[lkq + 0][lrow] = av.x;
        As[lkq + 1][lrow] = av.y;
        As[lkq + 2][lrow] = av.z;
        As[lkq + 3][lrow] = av.w;
        *(float4*)(&Bs[lk][lnq]) = bv;
        __syncthreads();

        // prefetch next tile while computing
        if (k0 + 16 < F_) {
            av = *(const float4*)(A + (size_t)(row0 + lrow) * F_ + (k0 + 16) + lkq);
            bv = *(const float4*)(Bw + (size_t)(k0 + 16 + lk) * N + col0 + lnq);
        }

#pragma unroll
        for (int kk = 0; kk < 16; kk++) {
            float4 a4 = *(const float4*)(&As[kk][ty * 4]);
            float4 b4 = *(const float4*)(&Bs[kk][tx * 4]);
            float2 bp0 = make_float2(b4.x, b4.y);
            float2 bp1 = make_float2(b4.z, b4.w);
            float aa[4] = {a4.x, a4.y, a4.z, a4.w};
#pragma unroll
            for (int i = 0; i < 4; i++) {
                float2 ad = dup2(aa[i]);
                fma2(acc[i][0], ad, bp0);
                fma2(acc[i][1], ad, bp1);
            }
        }
        __syncthreads();
    }
}

// Fused xw GEMMs (Wf and Wb): blockIdx.y in [0,48). y<24 -> Wf, else Wb.
__global__ void __launch_bounds__(256) gemm_xw_kernel(
    const float* __restrict__ x,
    const float* __restrict__ Wf, const float* __restrict__ Wb,
    const float* __restrict__ bf, const float* __restrict__ bb)
{
    __shared__ float As[16][64];
    __shared__ float Bs[16][64];
    int ysel = blockIdx.y >= 24;
    const float* Bw   = ysel ? Wb : Wf;
    const float* bias = ysel ? bb : bf;
    float* outp       = ysel ? g_xwb : g_xwf;
    int row0 = blockIdx.x * 64;
    int col0 = (blockIdx.y - (ysel ? 24 : 0)) * 64;

    float2 acc[4][2];
    gemm_tile(x, Bw, G_, row0, col0, acc, As, Bs);

    int tx = threadIdx.x & 15, ty = threadIdx.x >> 4;
#pragma unroll
    for (int i = 0; i < 4; i++) {
        int r = row0 + ty * 4 + i;
        int b = r >> 10;
        int t = r & 1023;
        int c = col0 + tx * 4;
        float v[4] = {acc[i][0].x, acc[i][0].y, acc[i][1].x, acc[i][1].y};
#pragma unroll
        for (int j = 0; j < 4; j++) {
            int g = c + j;
            outp[(size_t)t * GB_ + (size_t)g * B_ + b] = v[j] + bias[g];
        }
    }
}

// Residual projection GEMM (Wp)
__global__ void __launch_bounds__(256) gemm_p_kernel(
    const float* __restrict__ x, const float* __restrict__ Wp)
{
    __shared__ float As[16][64];
    __shared__ float Bs[16][64];
    int row0 = blockIdx.x * 64;
    int col0 = blockIdx.y * 64;

    float2 acc[4][2];
    gemm_tile(x, Wp, P_, row0, col0, acc, As, Bs);

    int tx = threadIdx.x & 15, ty = threadIdx.x >> 4;
#pragma unroll
    for (int i = 0; i < 4; i++) {
        int r = row0 + ty * 4 + i;
        int c = col0 + tx * 4;
        g_resid[(size_t)r * P_ + c + 0] = acc[i][0].x;
        g_resid[(size_t)r * P_ + c + 1] = acc[i][0].y;
        g_resid[(size_t)r * P_ + c + 2] = acc[i][1].x;
        g_resid[(size_t)r * P_ + c + 3] = acc[i][1].y;
    }
}

// ---------------------------------------------------------------------------
// GRU recurrence v14 = v12 core + monotonic-counter barrier.
// 128 blocks: 0..63 fwd, 64..127 bwd. Block owns 8 units of its direction.
// 512 threads = 16 warps: warp w -> (ch=w&1: col half = 12 U-cols,
// kw=w>>1: k-eighth = 32 kp). Lane covers batches (2*lane, 2*lane+1).
// h tile in 8 bursts of 4 LDG.128, register double-buffered.
// Sync: arrive = one atomicAdd on g_cnt[dir] (monotonic, no reset, no
// generation hop); wait = cnt >= 64*s, then __threadfence (acquire+IVALL,
// required: h lines go stale in L1 across parity revisits).
// SMEM: U 48KB [24][512] + partials 48KB [16][12][64] = 96KB.
// ---------------------------------------------------------------------------
__global__ void __launch_bounds__(512) gru_kernel(
    const float* __restrict__ Ufm, const float* __restrict__ Ubm,
    const float* __restrict__ bfv, const float* __restrict__ bbv)
{
    extern __shared__ float smem_[];
    float* Us   = smem_;                         // [24][512]
    float* part = smem_ + 24 * 512;              // [16][12][64]
#define PARTF(w, c, b) part[(((w) * 12 + (c)) << 6) + (b)]

    int tid = threadIdx.x;
    int dir = blockIdx.x >> 6;
    int jb  = blockIdx.x & 63;

    const float* Um    = dir ? Ubm : Ufm;
    const float* brv   = (dir ? bbv : bfv) + G_;   // recurrent bias b[1]
    const float* xw    = dir ? g_xwb : g_xwf;
    float*       hout  = dir ? g_hb  : g_hf;
    float*       hbase = g_hbuf + (size_t)dir * 2 * HB_;

    // Load U slice: col c = gate*8+uu -> Um[:, gate*512 + jb*8 + uu]
    for (int idx = tid; idx < 24 * 512; idx += 512) {
        int c = idx >> 9;
        int k = idx & 511;
        int g  = c >> 3;
        int uu = c & 7;
        Us[c * 512 + k] = Um[(size_t)k * G_ + g * U_ + jb * 8 + uu];
    }

    // compute role
    int w    = tid >> 5;        // 0..15
    int lane = tid & 31;
    int ch   = w & 1;           // col half: cols [ch*12, ch*12+12)
    int kw   = w >> 1;          // k-eighth: kp in [kw*32, kw*32+32)
    int cbase = ch * 12;

    // finalize role
    int uf   = tid >> 6;        // 0..7
    int bfin = tid & 63;
    int fug  = jb * 8 + uf;
    float brz = brv[fug];
    float brr = brv[U_ + fug];
    float brh = brv[2 * U_ + fug];
    // finalize col mapping: z col = uf (half 0), r col = 8+uf, h col = 16+uf (half 1)
    int chr = (uf >= 4) ? 1 : 0;
    int clr = (uf >= 4) ? (uf - 4) : (8 + uf);

    const float4* U4 = (const float4*)Us;   // index: c*128 + kw*16 + jj

    __syncthreads();

    for (int s = 0; s < T_; s++) {
        int tt = dir ? (T_ - 1 - s) : s;
        int par = s & 1;
        const float* HcF = hbase + (size_t)par * HB_;
        float*       HnF = hbase + (size_t)(par ^ 1) * HB_;
        // float4 view of H: index kp*32 + (b/2)
        const float4* Hq = (const float4*)HcF + (size_t)(kw * 32) * 32 + lane;

        // ---- operands that do NOT need the acquire: issue before the wait
        // xw was written before this kernel launched; hold was written by
        // THIS thread last step (same (uf,bfin) mapping).
        const float* XW = xw + (size_t)tt * GB_;
        float xz = XW[(0 * U_ + fug) * B_ + bfin];
        float xr = XW[(1 * U_ + fug) * B_ + bfin];
        float xh = XW[(2 * U_ + fug) * B_ + bfin];
        float2 hv = ((const float2*)HcF)[(size_t)(fug >> 1) * 64 + bfin];
        float hold = (uf & 1) ? hv.y : hv.x;

        // ---- wait for this direction's previous step (monotonic counter)
        if (s > 0) {
            if (tid == 0) {
                volatile unsigned* vc = &g_cnt[dir];
                unsigned target = (unsigned)(64 * s);
                while (*vc < target) { }
                __threadfence();   // acquire + L1D invalidate
            }
            __syncthreads();
        }

        // ---- dots: 12 cols x 32 kp x 2 batches per thread ----
        float2 acc0[12], acc1[12];
#pragma unroll
        for (int c = 0; c < 12; c++) { acc0[c] = make_float2(0.f, 0.f); acc1[c] = make_float2(0.f, 0.f); }

        // register double-buffered bursts: 4 float4 per burst = 4 kp = 2 dot iters
        float4 bufA[4], bufB[4];
#pragma unroll
        for (int j = 0; j < 4; j++) bufA[j] = Hq[(size_t)j * 32];

#pragma unroll
        for (int seg = 0; seg < 8; seg++) {
            float4* cur = (seg & 1) ? bufB : bufA;
            float4* nxt = (seg & 1) ? bufA : bufB;
            if (seg < 7) {   // issue next burst before consuming current
#pragma unroll
                for (int j = 0; j < 4; j++)
                    nxt[j] = Hq[(size_t)((seg + 1) * 4 + j) * 32];
            }
            // consume: kp 4*seg..4*seg+3 -> U4 indices kw*16 + 2*seg, +1
#pragma unroll
            for (int half = 0; half < 2; half++) {
                float4 h0 = cur[2 * half];       // kp even: b0=.xy b1=.zw
                float4 h1 = cur[2 * half + 1];   // kp odd
#pragma unroll
                for (int c = 0; c < 12; c++) {
                    float4 u = U4[(cbase + c) * 128 + kw * 16 + 2 * seg + half];
                    fma2(acc0[c], make_float2(u.x, u.y), make_float2(h0.x, h0.y));
                    fma2(acc1[c], make_float2(u.x, u.y), make_float2(h0.z, h0.w));
                    fma2(acc0[c], make_float2(u.z, u.w), make_float2(h1.x, h1.y));
                    fma2(acc1[c], make_float2(u.z, u.w), make_float2(h1.z, h1.w));
                }
            }
        }

        // fold even/odd k; write {b0, b1} as one float2
        float2* P2 = (float2*)part;
#pragma unroll
        for (int c = 0; c < 12; c++)
            P2[((w * 12 + c) << 5) + lane] =
                make_float2(acc0[c].x + acc0[c].y, acc1[c].x + acc1[c].y);
        __syncthreads();

        // ---- finalize: thread -> (unit uf, batch bfin) ----
        {
            float sz = 0.f, sr = 0.f, sh = 0.f;
#pragma unroll
            for (int k8 = 0; k8 < 8; k8++) {
                sz += PARTF(2 * k8 + 0,   uf,      bfin);   // z: col uf (half 0)
                sr += PARTF(2 * k8 + chr, clr,     bfin);   // r: col 8+uf
                sh += PARTF(2 * k8 + 1,   4 + uf,  bfin);   // h: col 16+uf (half 1)
            }
            float z  = 1.0f / (1.0f + expf(-(xz + sz + brz)));
            float r  = 1.0f / (1.0f + expf(-(xr + sr + brr)));
            float hh = tanhf(xh + r * (sh + brh));
            float hn = z * hold + (1.0f - z) * hh;

            HnF[(((size_t)(fug >> 1) * 64 + bfin) << 1) + (uf & 1)] = hn;
            __syncthreads();   // all Hn stores complete before release

            // arrive: single monotonic atomic (release); wait at next step top
            if (tid == 0) {
                __threadfence();
                atomicAdd(&g_cnt[dir], 1u);
            }
            // scattered per-timestep output store (overlaps release latency)
            hout[((size_t)bfin * T_ + tt) * U_ + fug] = hn;
        }
    }
#undef PARTF
}

// ---------------------------------------------------------------------------
// Epilogue: y = concat(hf,hb) + resid; LayerNorm over last dim (1024)
// ---------------------------------------------------------------------------
__global__ void __launch_bounds__(256) ln_kernel(
    const float* __restrict__ gamma, const float* __restrict__ beta,
    float* __restrict__ out)
{
    __shared__ float red[2][8];
    int row = blockIdx.x;       // b*T + t
    int tid = threadIdx.x;
    int c   = tid * 4;

    const float* hsrc = (tid < 128)
        ? (g_hf + (size_t)row * U_ + c)
        : (g_hb + (size_t)row * U_ + (c - U_));
    float4 h4 = *(const float4*)hsrc;
    float4 r4 = *(const float4*)(g_resid + (size_t)row * P_ + c);

    float y0 = h4.x + r4.x, y1 = h4.y + r4.y, y2 = h4.z + r4.z, y3 = h4.w + r4.w;
    float s  = y0 + y1 + y2 + y3;
    float s2 = y0 * y0 + y1 * y1 + y2 * y2 + y3 * y3;

#pragma unroll
    for (int off = 16; off > 0; off >>= 1) {
        s  += __shfl_xor_sync(0xFFFFFFFFu, s,  off);
        s2 += __shfl_xor_sync(0xFFFFFFFFu, s2, off);
    }
    int wid = tid >> 5, lane = tid & 31;
    if (lane == 0) { red[0][wid] = s; red[1][wid] = s2; }
    __syncthreads();
    s = 0.f; s2 = 0.f;
#pragma unroll
    for (int i = 0; i < 8; i++) { s += red[0][i]; s2 += red[1][i]; }

    float mu  = s * (1.0f / 1024.0f);
    float var = s2 * (1.0f / 1024.0f) - mu * mu;
    float inv = rsqrtf(var + EPS_);

    float4 g4 = *(const float4*)(gamma + c);
    float4 b4 = *(const float4*)(beta + c);
    float4 o;
    o.x = g4.x * (y0 - mu) * inv + b4.x;
    o.y = g4.y * (y1 - mu) * inv + b4.y;
    o.z = g4.z * (y2 - mu) * inv + b4.z;
    o.w = g4.w * (y3 - mu) * inv + b4.w;
    *(float4*)(out + (size_t)row * P_ + c) = o;
}

// ---------------------------------------------------------------------------
extern "C" void kernel_launch(void* const* d_in, const int* in_sizes, int n_in,
                              void* d_out, int out_size) {
    const float* x     = (const float*)d_in[0];
    const float* Wf    = (const float*)d_in[1];
    const float* Uf    = (const float*)d_in[2];
    const float* bf    = (const float*)d_in[3];
    const float* Wb    = (const float*)d_in[4];
    const float* Ub    = (const float*)d_in[5];
    const float* bb    = (const float*)d_in[6];
    const float* Wp    = (const float*)d_in[7];
    const float* gamma = (const float*)d_in[8];
    const float* beta  = (const float*)d_in[9];
    float* out = (float*)d_out;

    const int gru_smem = 24 * 512 * 4 + 16 * 12 * 64 * 4;  // 49152 + 49152 = 98304 B
    cudaFuncSetAttribute(gru_kernel, cudaFuncAttributeMaxDynamicSharedMemorySize, gru_smem);

    init_kernel<<<64, 256>>>();
    gemm_xw_kernel<<<dim3(1024, 48), 256>>>(x, Wf, Wb, bf, bb);
    gemm_p_kernel<<<dim3(1024, 16), 256>>>(x, Wp);
    gru_kernel<<<128, 512, gru_smem>>>(Uf, Ub, bf, bb);
    ln_kernel<<<B_ * T_, 256>>>(gamma, beta, out);
}